// round 16
// baseline (speedup 1.0000x reference)
#include <cuda_runtime.h>
#include <math.h>

#define NH  4096   // n_history
#define DIM 512    // embed dim
#define HID 8      // MLP hidden

// 64 MB scratch for exp-scores, plus reciprocal rowsums. Static __device__
// arrays are the sanctioned no-alloc scratch mechanism.
static __device__ __align__(16) float g_E[(size_t)NH * NH];
static __device__ float g_rinv[NH];

// ---------------------------------------------------------------------------
// Phase 1: E[i][j] = exp( (Q_i . K_j) / sqrt(D) * sigmoid(MLP(|t_i - t_j|)) )
// Classic 128x128x16 SGEMM tile, 256 threads, 8x8 micro-tile, double-buffered.
// ---------------------------------------------------------------------------
#define BM1 128
#define BN1 128
#define BK1 16

__global__ __launch_bounds__(256, 2) void phase1_kernel(
    const float* __restrict__ Q, const float* __restrict__ Kh,
    const float* __restrict__ times,
    const float* __restrict__ w1, const float* __restrict__ b1,
    const float* __restrict__ w2, const float* __restrict__ b2)
{
    __shared__ float As[2][BK1][BM1];
    __shared__ float Bs[2][BK1][BN1];
    __shared__ float tR[BM1];
    __shared__ float tC[BN1];
    __shared__ float sW[3 * HID + 1];

    const int t  = threadIdx.x;
    const int tx = t & 15;          // 16 column groups (4 + 4 cols each)
    const int ty = t >> 4;          // 16 row groups (8 rows each)
    const int rowBase = blockIdx.y * BM1;
    const int colBase = blockIdx.x * BN1;

    if (t < BM1) tR[t] = times[rowBase + t];
    else         tC[t - BM1] = times[colBase + (t - BM1)];
    if (t < HID) {
        sW[t]           = w1[t];
        sW[HID + t]     = b1[t];
        sW[2 * HID + t] = w2[t];
    }
    if (t == 31) sW[3 * HID] = b2[0];

    // Tile-load mapping: 512 float4 per tile (A and B each), 2 per thread.
    const int id0 = t, id1 = t + 256;
    const int ar0 = id0 >> 2, ac0 = (id0 & 3) << 2;
    const int ar1 = id1 >> 2, ac1 = (id1 & 3) << 2;

    const float* Arow0 = Q  + (size_t)(rowBase + ar0) * DIM + ac0;
    const float* Arow1 = Q  + (size_t)(rowBase + ar1) * DIM + ac1;
    const float* Brow0 = Kh + (size_t)(colBase + ar0) * DIM + ac0;
    const float* Brow1 = Kh + (size_t)(colBase + ar1) * DIM + ac1;

    float acc[8][8];
#pragma unroll
    for (int i = 0; i < 8; i++)
#pragma unroll
        for (int j = 0; j < 8; j++) acc[i][j] = 0.f;

    // ---- load tile 0 (transposed into smem) ----
    {
        float4 a0 = *(const float4*)(Arow0);
        float4 a1 = *(const float4*)(Arow1);
        float4 c0 = *(const float4*)(Brow0);
        float4 c1 = *(const float4*)(Brow1);
        As[0][ac0+0][ar0] = a0.x; As[0][ac0+1][ar0] = a0.y;
        As[0][ac0+2][ar0] = a0.z; As[0][ac0+3][ar0] = a0.w;
        As[0][ac1+0][ar1] = a1.x; As[0][ac1+1][ar1] = a1.y;
        As[0][ac1+2][ar1] = a1.z; As[0][ac1+3][ar1] = a1.w;
        Bs[0][ac0+0][ar0] = c0.x; Bs[0][ac0+1][ar0] = c0.y;
        Bs[0][ac0+2][ar0] = c0.z; Bs[0][ac0+3][ar0] = c0.w;
        Bs[0][ac1+0][ar1] = c1.x; Bs[0][ac1+1][ar1] = c1.y;
        Bs[0][ac1+2][ar1] = c1.z; Bs[0][ac1+3][ar1] = c1.w;
    }
    __syncthreads();

    int buf = 0;
    for (int kt = 0; kt < DIM; kt += BK1) {
        float4 pa0, pa1, pb0, pb1;
        const bool more = (kt + BK1) < DIM;
        if (more) {
            pa0 = *(const float4*)(Arow0 + kt + BK1);
            pa1 = *(const float4*)(Arow1 + kt + BK1);
            pb0 = *(const float4*)(Brow0 + kt + BK1);
            pb1 = *(const float4*)(Brow1 + kt + BK1);
        }
#pragma unroll
        for (int k = 0; k < BK1; k++) {
            float4 a0 = *(const float4*)&As[buf][k][ty * 8];
            float4 a1 = *(const float4*)&As[buf][k][ty * 8 + 4];
            float4 c0 = *(const float4*)&Bs[buf][k][tx * 4];
            float4 c1 = *(const float4*)&Bs[buf][k][64 + tx * 4];
            float av[8] = {a0.x,a0.y,a0.z,a0.w,a1.x,a1.y,a1.z,a1.w};
            float bv[8] = {c0.x,c0.y,c0.z,c0.w,c1.x,c1.y,c1.z,c1.w};
#pragma unroll
            for (int i = 0; i < 8; i++)
#pragma unroll
                for (int j = 0; j < 8; j++)
                    acc[i][j] = fmaf(av[i], bv[j], acc[i][j]);
        }
        if (more) {
            const int nb = buf ^ 1;
            As[nb][ac0+0][ar0] = pa0.x; As[nb][ac0+1][ar0] = pa0.y;
            As[nb][ac0+2][ar0] = pa0.z; As[nb][ac0+3][ar0] = pa0.w;
            As[nb][ac1+0][ar1] = pa1.x; As[nb][ac1+1][ar1] = pa1.y;
            As[nb][ac1+2][ar1] = pa1.z; As[nb][ac1+3][ar1] = pa1.w;
            Bs[nb][ac0+0][ar0] = pb0.x; Bs[nb][ac0+1][ar0] = pb0.y;
            Bs[nb][ac0+2][ar0] = pb0.z; Bs[nb][ac0+3][ar0] = pb0.w;
            Bs[nb][ac1+0][ar1] = pb1.x; Bs[nb][ac1+1][ar1] = pb1.y;
            Bs[nb][ac1+2][ar1] = pb1.z; Bs[nb][ac1+3][ar1] = pb1.w;
            __syncthreads();
            buf = nb;
        }
    }

    // ---- epilogue: time-weight MLP + sigmoid + exp, store E ----
    const float rsD = 0.044194173824159216f;   // 1/sqrt(512)
    float lw1[HID], lb1[HID], lw2[HID];
#pragma unroll
    for (int h = 0; h < HID; h++) {
        lw1[h] = sW[h]; lb1[h] = sW[HID + h]; lw2[h] = sW[2 * HID + h];
    }
    const float lb2 = sW[3 * HID];

#pragma unroll
    for (int ii = 0; ii < 8; ii++) {
        const int   gi = rowBase + ty * 8 + ii;
        const float ti = tR[ty * 8 + ii];
        float outv[8];
#pragma unroll
        for (int jj = 0; jj < 8; jj++) {
            const int cj = (jj < 4) ? (tx * 4 + jj) : (64 + tx * 4 + (jj - 4));
            const float dt = fabsf(ti - tC[cj]);
            float s = lb2;
#pragma unroll
            for (int h = 0; h < HID; h++) {
                float hk = fmaxf(fmaf(dt, lw1[h], lb1[h]), 0.f);
                s = fmaf(hk, lw2[h], s);
            }
            const float tw = 1.f / (1.f + __expf(-s));
            outv[jj] = __expf(acc[ii][jj] * rsD * tw);
        }
        float* dst = g_E + (size_t)gi * NH + colBase;
        *(float4*)(dst + tx * 4)      = make_float4(outv[0], outv[1], outv[2], outv[3]);
        *(float4*)(dst + 64 + tx * 4) = make_float4(outv[4], outv[5], outv[6], outv[7]);
    }
}

// ---------------------------------------------------------------------------
// Rowsum: deterministic reciprocal rowsums of E (no atomics).
// ---------------------------------------------------------------------------
__global__ __launch_bounds__(128) void rowsum_kernel()
{
    const int i = blockIdx.x;
    const float4* row = (const float4*)(g_E + (size_t)i * NH);
    float s = 0.f;
#pragma unroll
    for (int j = 0; j < (NH / 4) / 128; j++) {   // 8 float4 per thread
        float4 v = row[threadIdx.x + j * 128];
        s += (v.x + v.y) + (v.z + v.w);
    }
#pragma unroll
    for (int o = 16; o > 0; o >>= 1)
        s += __shfl_xor_sync(0xffffffffu, s, o);
    __shared__ float ws[4];
    const int lane = threadIdx.x & 31, w = threadIdx.x >> 5;
    if (lane == 0) ws[w] = s;
    __syncthreads();
    if (threadIdx.x == 0) {
        const float tot = (ws[0] + ws[1]) + (ws[2] + ws[3]);
        g_rinv[i] = 1.f / tot;
    }
}

// ---------------------------------------------------------------------------
// Phase 2: O = (E @ V) * rinv.  128x64x16 tiles, 256 threads, 8x4 micro-tile.
// ---------------------------------------------------------------------------
#define BM2 128
#define BN2 64
#define BK2 16

__global__ __launch_bounds__(256, 2) void phase2_kernel(
    const float* __restrict__ V, float* __restrict__ out)
{
    __shared__ float As[2][BK2][BM2];
    __shared__ float Bs[2][BK2][BN2];

    const int t  = threadIdx.x;
    const int tx = t & 15;          // 16 col groups * 4 cols = 64
    const int ty = t >> 4;          // 16 row groups * 8 rows = 128
    const int rowBase = blockIdx.y * BM2;
    const int colBase = blockIdx.x * BN2;

    // A (E) tile: 128x16 -> transposed store, 2 float4 per thread.
    const int id0 = t, id1 = t + 256;
    const int ar0 = id0 >> 2, ac0 = (id0 & 3) << 2;
    const int ar1 = id1 >> 2, ac1 = (id1 & 3) << 2;
    const float* Arow0 = g_E + (size_t)(rowBase + ar0) * NH + ac0;
    const float* Arow1 = g_E + (size_t)(rowBase + ar1) * NH + ac1;

    // B (V) tile: 16x64 row-major, direct store, 1 float4 per thread.
    const int br = t >> 4;           // k-row within tile
    const int bc = (t & 15) << 2;    // col within tile
    const float* Brow = V + (size_t)br * DIM + colBase + bc;

    float acc[8][4];
#pragma unroll
    for (int i = 0; i < 8; i++)
#pragma unroll
        for (int j = 0; j < 4; j++) acc[i][j] = 0.f;

    // ---- load tile 0 ----
    {
        float4 a0 = *(const float4*)(Arow0);
        float4 a1 = *(const float4*)(Arow1);
        float4 bv = *(const float4*)(Brow);
        As[0][ac0+0][ar0] = a0.x; As[0][ac0+1][ar0] = a0.y;
        As[0][ac0+2][ar0] = a0.z; As[0][ac0+3][ar0] = a0.w;
        As[0][ac1+0][ar1] = a1.x; As[0][ac1+1][ar1] = a1.y;
        As[0][ac1+2][ar1] = a1.z; As[0][ac1+3][ar1] = a1.w;
        *(float4*)&Bs[0][br][bc] = bv;
    }
    __syncthreads();

    int buf = 0;
    for (int kt = 0; kt < NH; kt += BK2) {
        float4 pa0, pa1, pbv;
        const bool more = (kt + BK2) < NH;
        if (more) {
            pa0 = *(const float4*)(Arow0 + kt + BK2);
            pa1 = *(const float4*)(Arow1 + kt + BK2);
            pbv = *(const float4*)(Brow + (size_t)(kt + BK2) * DIM);
        }
#pragma unroll
        for (int k = 0; k < BK2; k++) {
            float4 a0 = *(const float4*)&As[buf][k][ty * 8];
            float4 a1 = *(const float4*)&As[buf][k][ty * 8 + 4];
            float4 bv = *(const float4*)&Bs[buf][k][tx * 4];
            float av[8] = {a0.x,a0.y,a0.z,a0.w,a1.x,a1.y,a1.z,a1.w};
            float bb[4] = {bv.x,bv.y,bv.z,bv.w};
#pragma unroll
            for (int i = 0; i < 8; i++)
#pragma unroll
                for (int j = 0; j < 4; j++)
                    acc[i][j] = fmaf(av[i], bb[j], acc[i][j]);
        }
        if (more) {
            const int nb = buf ^ 1;
            As[nb][ac0+0][ar0] = pa0.x; As[nb][ac0+1][ar0] = pa0.y;
            As[nb][ac0+2][ar0] = pa0.z; As[nb][ac0+3][ar0] = pa0.w;
            As[nb][ac1+0][ar1] = pa1.x; As[nb][ac1+1][ar1] = pa1.y;
            As[nb][ac1+2][ar1] = pa1.z; As[nb][ac1+3][ar1] = pa1.w;
            *(float4*)&Bs[nb][br][bc] = pbv;
            __syncthreads();
            buf = nb;
        }
    }

    // ---- epilogue: normalize and store ----
#pragma unroll
    for (int ii = 0; ii < 8; ii++) {
        const int gi = rowBase + ty * 8 + ii;
        const float r = g_rinv[gi];
        float4 o = make_float4(acc[ii][0] * r, acc[ii][1] * r,
                               acc[ii][2] * r, acc[ii][3] * r);
        *(float4*)(out + (size_t)gi * DIM + colBase + tx * 4) = o;
    }
}

// ---------------------------------------------------------------------------
// Launch
// ---------------------------------------------------------------------------
extern "C" void kernel_launch(void* const* d_in, const int* in_sizes, int n_in,
                              void* d_out, int out_size)
{
    (void)in_sizes; (void)n_in; (void)out_size;
    const float* Q  = (const float*)d_in[0];   // query_code_embeds [N,D]
    const float* Kh = (const float*)d_in[1];   // hist_embeddings   [N,D]
    const float* tm = (const float*)d_in[2];   // hist_times        [N]
    const float* w1 = (const float*)d_in[3];   // tw_w1 [1,H]
    const float* b1 = (const float*)d_in[4];   // tw_b1 [H]
    const float* w2 = (const float*)d_in[5];   // tw_w2 [H,1]
    const float* b2 = (const float*)d_in[6];   // tw_b2 [1]
    float* out = (float*)d_out;                // [N,D] float32

    phase1_kernel<<<dim3(NH / BN1, NH / BM1), 256>>>(Q, Kh, tm, w1, b1, w2, b2);
    rowsum_kernel<<<NH, 128>>>();
    phase2_kernel<<<dim3(DIM / BN2, NH / BM2), 256>>>(Kh, out);
}

// round 17
// speedup vs baseline: 1.0034x; 1.0034x over previous
#include <cuda_runtime.h>
#include <math.h>

#define NH  4096   // n_history
#define DIM 512    // embed dim
#define HID 8      // MLP hidden

// 64 MB scratch for exp-scores, plus reciprocal rowsums. Static __device__
// arrays are the sanctioned no-alloc scratch mechanism.
static __device__ __align__(16) float g_E[(size_t)NH * NH];
static __device__ float g_rinv[NH];

// ---------------------------------------------------------------------------
// Phase 1: E[i][j] = exp( (Q_i . K_j) / sqrt(D) * sigmoid(MLP(|t_i - t_j|)) )
// Classic 128x128x16 SGEMM tile, 256 threads, 8x8 micro-tile, double-buffered.
// ---------------------------------------------------------------------------
#define BM1 128
#define BN1 128
#define BK1 16

__global__ __launch_bounds__(256, 2) void phase1_kernel(
    const float* __restrict__ Q, const float* __restrict__ Kh,
    const float* __restrict__ times,
    const float* __restrict__ w1, const float* __restrict__ b1,
    const float* __restrict__ w2, const float* __restrict__ b2)
{
    __shared__ float As[2][BK1][BM1];
    __shared__ float Bs[2][BK1][BN1];
    __shared__ float tR[BM1];
    __shared__ float tC[BN1];
    __shared__ float sW[3 * HID + 1];

    const int t  = threadIdx.x;
    const int tx = t & 15;          // 16 column groups (4 + 4 cols each)
    const int ty = t >> 4;          // 16 row groups (8 rows each)
    const int rowBase = blockIdx.y * BM1;
    const int colBase = blockIdx.x * BN1;

    if (t < BM1) tR[t] = times[rowBase + t];
    else         tC[t - BM1] = times[colBase + (t - BM1)];
    if (t < HID) {
        sW[t]           = w1[t];
        sW[HID + t]     = b1[t];
        sW[2 * HID + t] = w2[t];
    }
    if (t == 31) sW[3 * HID] = b2[0];

    // Tile-load mapping: 512 float4 per tile (A and B each), 2 per thread.
    const int id0 = t, id1 = t + 256;
    const int ar0 = id0 >> 2, ac0 = (id0 & 3) << 2;
    const int ar1 = id1 >> 2, ac1 = (id1 & 3) << 2;

    const float* Arow0 = Q  + (size_t)(rowBase + ar0) * DIM + ac0;
    const float* Arow1 = Q  + (size_t)(rowBase + ar1) * DIM + ac1;
    const float* Brow0 = Kh + (size_t)(colBase + ar0) * DIM + ac0;
    const float* Brow1 = Kh + (size_t)(colBase + ar1) * DIM + ac1;

    float acc[8][8];
#pragma unroll
    for (int i = 0; i < 8; i++)
#pragma unroll
        for (int j = 0; j < 8; j++) acc[i][j] = 0.f;

    // ---- load tile 0 (transposed into smem) ----
    {
        float4 a0 = *(const float4*)(Arow0);
        float4 a1 = *(const float4*)(Arow1);
        float4 c0 = *(const float4*)(Brow0);
        float4 c1 = *(const float4*)(Brow1);
        As[0][ac0+0][ar0] = a0.x; As[0][ac0+1][ar0] = a0.y;
        As[0][ac0+2][ar0] = a0.z; As[0][ac0+3][ar0] = a0.w;
        As[0][ac1+0][ar1] = a1.x; As[0][ac1+1][ar1] = a1.y;
        As[0][ac1+2][ar1] = a1.z; As[0][ac1+3][ar1] = a1.w;
        Bs[0][ac0+0][ar0] = c0.x; Bs[0][ac0+1][ar0] = c0.y;
        Bs[0][ac0+2][ar0] = c0.z; Bs[0][ac0+3][ar0] = c0.w;
        Bs[0][ac1+0][ar1] = c1.x; Bs[0][ac1+1][ar1] = c1.y;
        Bs[0][ac1+2][ar1] = c1.z; Bs[0][ac1+3][ar1] = c1.w;
    }
    __syncthreads();

    int buf = 0;
    for (int kt = 0; kt < DIM; kt += BK1) {
        float4 pa0, pa1, pb0, pb1;
        const bool more = (kt + BK1) < DIM;
        if (more) {
            pa0 = *(const float4*)(Arow0 + kt + BK1);
            pa1 = *(const float4*)(Arow1 + kt + BK1);
            pb0 = *(const float4*)(Brow0 + kt + BK1);
            pb1 = *(const float4*)(Brow1 + kt + BK1);
        }
#pragma unroll
        for (int k = 0; k < BK1; k++) {
            float4 a0 = *(const float4*)&As[buf][k][ty * 8];
            float4 a1 = *(const float4*)&As[buf][k][ty * 8 + 4];
            float4 c0 = *(const float4*)&Bs[buf][k][tx * 4];
            float4 c1 = *(const float4*)&Bs[buf][k][64 + tx * 4];
            float av[8] = {a0.x,a0.y,a0.z,a0.w,a1.x,a1.y,a1.z,a1.w};
            float bv[8] = {c0.x,c0.y,c0.z,c0.w,c1.x,c1.y,c1.z,c1.w};
#pragma unroll
            for (int i = 0; i < 8; i++)
#pragma unroll
                for (int j = 0; j < 8; j++)
                    acc[i][j] = fmaf(av[i], bv[j], acc[i][j]);
        }
        if (more) {
            const int nb = buf ^ 1;
            As[nb][ac0+0][ar0] = pa0.x; As[nb][ac0+1][ar0] = pa0.y;
            As[nb][ac0+2][ar0] = pa0.z; As[nb][ac0+3][ar0] = pa0.w;
            As[nb][ac1+0][ar1] = pa1.x; As[nb][ac1+1][ar1] = pa1.y;
            As[nb][ac1+2][ar1] = pa1.z; As[nb][ac1+3][ar1] = pa1.w;
            Bs[nb][ac0+0][ar0] = pb0.x; Bs[nb][ac0+1][ar0] = pb0.y;
            Bs[nb][ac0+2][ar0] = pb0.z; Bs[nb][ac0+3][ar0] = pb0.w;
            Bs[nb][ac1+0][ar1] = pb1.x; Bs[nb][ac1+1][ar1] = pb1.y;
            Bs[nb][ac1+2][ar1] = pb1.z; Bs[nb][ac1+3][ar1] = pb1.w;
            __syncthreads();
            buf = nb;
        }
    }

    // ---- epilogue: time-weight MLP + sigmoid + exp, store E ----
    const float rsD = 0.044194173824159216f;   // 1/sqrt(512)
    float lw1[HID], lb1[HID], lw2[HID];
#pragma unroll
    for (int h = 0; h < HID; h++) {
        lw1[h] = sW[h]; lb1[h] = sW[HID + h]; lw2[h] = sW[2 * HID + h];
    }
    const float lb2 = sW[3 * HID];

#pragma unroll
    for (int ii = 0; ii < 8; ii++) {
        const int   gi = rowBase + ty * 8 + ii;
        const float ti = tR[ty * 8 + ii];
        float outv[8];
#pragma unroll
        for (int jj = 0; jj < 8; jj++) {
            const int cj = (jj < 4) ? (tx * 4 + jj) : (64 + tx * 4 + (jj - 4));
            const float dt = fabsf(ti - tC[cj]);
            float s = lb2;
#pragma unroll
            for (int h = 0; h < HID; h++) {
                float hk = fmaxf(fmaf(dt, lw1[h], lb1[h]), 0.f);
                s = fmaf(hk, lw2[h], s);
            }
            const float tw = 1.f / (1.f + __expf(-s));
            outv[jj] = __expf(acc[ii][jj] * rsD * tw);
        }
        float* dst = g_E + (size_t)gi * NH + colBase;
        *(float4*)(dst + tx * 4)      = make_float4(outv[0], outv[1], outv[2], outv[3]);
        *(float4*)(dst + 64 + tx * 4) = make_float4(outv[4], outv[5], outv[6], outv[7]);
    }
}

// ---------------------------------------------------------------------------
// Rowsum: deterministic reciprocal rowsums of E (no atomics).
// ---------------------------------------------------------------------------
__global__ __launch_bounds__(128) void rowsum_kernel()
{
    const int i = blockIdx.x;
    const float4* row = (const float4*)(g_E + (size_t)i * NH);
    float s = 0.f;
#pragma unroll
    for (int j = 0; j < (NH / 4) / 128; j++) {   // 8 float4 per thread
        float4 v = row[threadIdx.x + j * 128];
        s += (v.x + v.y) + (v.z + v.w);
    }
#pragma unroll
    for (int o = 16; o > 0; o >>= 1)
        s += __shfl_xor_sync(0xffffffffu, s, o);
    __shared__ float ws[4];
    const int lane = threadIdx.x & 31, w = threadIdx.x >> 5;
    if (lane == 0) ws[w] = s;
    __syncthreads();
    if (threadIdx.x == 0) {
        const float tot = (ws[0] + ws[1]) + (ws[2] + ws[3]);
        g_rinv[i] = 1.f / tot;
    }
}

// ---------------------------------------------------------------------------
// Phase 2: O = (E @ V) * rinv.  128x64x16 tiles, 256 threads, 8x4 micro-tile.
// ---------------------------------------------------------------------------
#define BM2 128
#define BN2 64
#define BK2 16

__global__ __launch_bounds__(256, 2) void phase2_kernel(
    const float* __restrict__ V, float* __restrict__ out)
{
    __shared__ float As[2][BK2][BM2];
    __shared__ float Bs[2][BK2][BN2];

    const int t  = threadIdx.x;
    const int tx = t & 15;          // 16 col groups * 4 cols = 64
    const int ty = t >> 4;          // 16 row groups * 8 rows = 128
    const int rowBase = blockIdx.y * BM2;
    const int colBase = blockIdx.x * BN2;

    // A (E) tile: 128x16 -> transposed store, 2 float4 per thread.
    const int id0 = t, id1 = t + 256;
    const int ar0 = id0 >> 2, ac0 = (id0 & 3) << 2;
    const int ar1 = id1 >> 2, ac1 = (id1 & 3) << 2;
    const float* Arow0 = g_E + (size_t)(rowBase + ar0) * NH + ac0;
    const float* Arow1 = g_E + (size_t)(rowBase + ar1) * NH + ac1;

    // B (V) tile: 16x64 row-major, direct store, 1 float4 per thread.
    const int br = t >> 4;           // k-row within tile
    const int bc = (t & 15) << 2;    // col within tile
    const float* Brow = V + (size_t)br * DIM + colBase + bc;

    float acc[8][4];
#pragma unroll
    for (int i = 0; i < 8; i++)
#pragma unroll
        for (int j = 0; j < 4; j++) acc[i][j] = 0.f;

    // ---- load tile 0 ----
    {
        float4 a0 = *(const float4*)(Arow0);
        float4 a1 = *(const float4*)(Arow1);
        float4 bv = *(const float4*)(Brow);
        As[0][ac0+0][ar0] = a0.x; As[0][ac0+1][ar0] = a0.y;
        As[0][ac0+2][ar0] = a0.z; As[0][ac0+3][ar0] = a0.w;
        As[0][ac1+0][ar1] = a1.x; As[0][ac1+1][ar1] = a1.y;
        As[0][ac1+2][ar1] = a1.z; As[0][ac1+3][ar1] = a1.w;
        *(float4*)&Bs[0][br][bc] = bv;
    }
    __syncthreads();

    int buf = 0;
    for (int kt = 0; kt < NH; kt += BK2) {
        float4 pa0, pa1, pbv;
        const bool more = (kt + BK2) < NH;
        if (more) {
            pa0 = *(const float4*)(Arow0 + kt + BK2);
            pa1 = *(const float4*)(Arow1 + kt + BK2);
            pbv = *(const float4*)(Brow + (size_t)(kt + BK2) * DIM);
        }
#pragma unroll
        for (int k = 0; k < BK2; k++) {
            float4 a0 = *(const float4*)&As[buf][k][ty * 8];
            float4 a1 = *(const float4*)&As[buf][k][ty * 8 + 4];
            float4 bv = *(const float4*)&Bs[buf][k][tx * 4];
            float av[8] = {a0.x,a0.y,a0.z,a0.w,a1.x,a1.y,a1.z,a1.w};
            float bb[4] = {bv.x,bv.y,bv.z,bv.w};
#pragma unroll
            for (int i = 0; i < 8; i++)
#pragma unroll
                for (int j = 0; j < 4; j++)
                    acc[i][j] = fmaf(av[i], bb[j], acc[i][j]);
        }
        if (more) {
            const int nb = buf ^ 1;
            As[nb][ac0+0][ar0] = pa0.x; As[nb][ac0+1][ar0] = pa0.y;
            As[nb][ac0+2][ar0] = pa0.z; As[nb][ac0+3][ar0] = pa0.w;
            As[nb][ac1+0][ar1] = pa1.x; As[nb][ac1+1][ar1] = pa1.y;
            As[nb][ac1+2][ar1] = pa1.z; As[nb][ac1+3][ar1] = pa1.w;
            *(float4*)&Bs[nb][br][bc] = pbv;
            __syncthreads();
            buf = nb;
        }
    }

    // ---- epilogue: normalize and store ----
#pragma unroll
    for (int ii = 0; ii < 8; ii++) {
        const int gi = rowBase + ty * 8 + ii;
        const float r = g_rinv[gi];
        float4 o = make_float4(acc[ii][0] * r, acc[ii][1] * r,
                               acc[ii][2] * r, acc[ii][3] * r);
        *(float4*)(out + (size_t)gi * DIM + colBase + tx * 4) = o;
    }
}

// ---------------------------------------------------------------------------
// Launch
// ---------------------------------------------------------------------------
extern "C" void kernel_launch(void* const* d_in, const int* in_sizes, int n_in,
                              void* d_out, int out_size)
{
    (void)in_sizes; (void)n_in; (void)out_size;
    const float* Q  = (const float*)d_in[0];   // query_code_embeds [N,D]
    const float* Kh = (const float*)d_in[1];   // hist_embeddings   [N,D]
    const float* tm = (const float*)d_in[2];   // hist_times        [N]
    const float* w1 = (const float*)d_in[3];   // tw_w1 [1,H]
    const float* b1 = (const float*)d_in[4];   // tw_b1 [H]
    const float* w2 = (const float*)d_in[5];   // tw_w2 [H,1]
    const float* b2 = (const float*)d_in[6];   // tw_b2 [1]
    float* out = (float*)d_out;                // [N,D] float32

    phase1_kernel<<<dim3(NH / BN1, NH / BM1), 256>>>(Q, Kh, tm, w1, b1, w2, b2);
    rowsum_kernel<<<NH, 128>>>();
    phase2_kernel<<<dim3(DIM / BN2, NH / BM2), 256>>>(Kh, out);
}